// round 1
// baseline (speedup 1.0000x reference)
#include <cuda_runtime.h>
#include <math.h>
#include <float.h>

#define B   2
#define P   19248
#define NC  100
#define NK  20
#define GP  1024   /* 32*32 */
#define HP  138
#define HIMG 550
#define DM  32

__device__ float d_confp[B*P];
__device__ float d_sconf[B*NC];
__device__ int   d_sidx[B*NC];
__device__ float d_g[B*NC*GP];
__device__ float d_gsum[B*NC];
__device__ float d_iou[B*NC*NC];
__device__ float d_kloc[B*NK*4];
__device__ float d_kmask[B*NK*DM];
__device__ float d_kconf[B*NK];
__device__ float d_fconf[B*HP*HP];
__device__ double d_ae_acc;
__device__ double d_var_acc;

__global__ void initK() { d_ae_acc = 0.0; d_var_acc = 0.0; }

__global__ void confpK(const float* __restrict__ conf) {
    int t = blockIdx.x * blockDim.x + threadIdx.x;
    if (t < B*P) {
        float c0 = conf[2*t], c1 = conf[2*t+1];
        d_confp[t] = 1.0f / (1.0f + expf(c0 - c1));   // softmax(...)[:,1]
    }
}

// ---- top-100 per batch: iterative argmax over shared copy ----
__global__ void topkK() {
    extern __shared__ float sv[];        // P floats
    __shared__ float wv[32];
    __shared__ int   wi[32];
    int b = blockIdx.x;
    int tid = threadIdx.x;
    for (int p = tid; p < P; p += 1024) sv[p] = d_confp[b*P + p];
    __syncthreads();
    for (int it = 0; it < NC; it++) {
        float bv = -FLT_MAX; int bi = P;
        for (int p = tid; p < P; p += 1024) {
            float v = sv[p];
            if (v > bv) { bv = v; bi = p; }   // ascending p -> lower index wins ties
        }
        #pragma unroll
        for (int off = 16; off > 0; off >>= 1) {
            float ov = __shfl_down_sync(0xffffffffu, bv, off);
            int   oi = __shfl_down_sync(0xffffffffu, bi, off);
            if (ov > bv || (ov == bv && oi < bi)) { bv = ov; bi = oi; }
        }
        if ((tid & 31) == 0) { wv[tid >> 5] = bv; wi[tid >> 5] = bi; }
        __syncthreads();
        if (tid < 32) {
            bv = wv[tid]; bi = wi[tid];
            #pragma unroll
            for (int off = 16; off > 0; off >>= 1) {
                float ov = __shfl_down_sync(0xffffffffu, bv, off);
                int   oi = __shfl_down_sync(0xffffffffu, bi, off);
                if (ov > bv || (ov == bv && oi < bi)) { bv = ov; bi = oi; }
            }
            if (tid == 0) {
                d_sconf[b*NC + it] = bv;
                d_sidx[b*NC + it]  = bi;
                sv[bi] = -FLT_MAX;
            }
        }
        __syncthreads();
    }
}

// ---- render 32x32 gaussians for the top-100 boxes, plus per-box sums ----
__global__ void gaussK(const float* __restrict__ loc) {
    __shared__ float red[32];
    int blk = blockIdx.x;                // b*NC + i
    int b = blk / NC;
    int tid = threadIdx.x;               // 1024
    int gidx = d_sidx[blk];
    const float* l = loc + ((size_t)b*P + gidx) * 4;
    float cx = l[0], cy = l[1], w = l[2], h = l[3];
    int y = tid >> 5, x = tid & 31;
    float xs = (x + 0.5f) / 32.0f;
    float ys = (y + 0.5f) / 32.0f;
    float dx = (xs - cx) / (w + 1e-4f);
    float dy = (ys - cy) / (h + 1e-4f);
    float g = expf(-0.5f * (dx*dx + dy*dy));
    d_g[blk*GP + tid] = g;
    float s = g;
    #pragma unroll
    for (int off = 16; off > 0; off >>= 1) s += __shfl_down_sync(0xffffffffu, s, off);
    if ((tid & 31) == 0) red[tid >> 5] = s;
    __syncthreads();
    if (tid < 32) {
        s = red[tid];
        #pragma unroll
        for (int off = 16; off > 0; off >>= 1) s += __shfl_down_sync(0xffffffffu, s, off);
        if (tid == 0) d_gsum[blk] = s;
    }
}

// ---- pairwise gaussian IoU, only j > i ----
__global__ void iouK() {
    __shared__ float sgi[GP];
    int blk = blockIdx.x;                // b*NC + i
    int b = blk / NC, i = blk % NC;
    int tid = threadIdx.x;               // 256
    const float* gi = d_g + blk*GP;
    for (int e = tid; e < GP; e += 256) sgi[e] = gi[e];
    __syncthreads();
    int warp = tid >> 5, lane = tid & 31;
    float si = d_gsum[blk];
    for (int j = i + 1 + warp; j < NC; j += 8) {
        const float* gj = d_g + (b*NC + j)*GP;
        float acc = 0.f;
        #pragma unroll 4
        for (int e = lane; e < GP; e += 32) acc += fminf(sgi[e], gj[e]);
        #pragma unroll
        for (int off = 16; off > 0; off >>= 1) acc += __shfl_down_sync(0xffffffffu, acc, off);
        if (lane == 0) {
            float sj = d_gsum[b*NC + j];
            d_iou[(b*NC + i)*NC + j] = acc / (si + sj - acc);
        }
    }
}

// ---- iou_max, keep-20 selection, gathers, AE loss term ----
__global__ void keepK(const float* __restrict__ loc, const float* __restrict__ mask) {
    __shared__ float siou[NC*NC];        // 40 KB
    __shared__ float smax[NC];
    __shared__ int   skeep[NK];
    __shared__ float sred[128];
    int b = blockIdx.x, tid = threadIdx.x;   // 128 threads
    for (int t = tid; t < NC*NC; t += 128) {
        int i = t / NC, j = t % NC;
        siou[t] = (j > i) ? d_iou[(b*NC + i)*NC + j] : 0.f;
    }
    __syncthreads();
    if (tid < NC) {
        float m = 0.f;                       // triu zeros dominate when empty
        for (int i = 0; i < tid; i++) m = fmaxf(m, siou[i*NC + tid]);
        smax[tid] = m;
    }
    __syncthreads();
    if (tid == 0) {
        bool taken[NC];
        for (int j = 0; j < NC; j++) taken[j] = false;
        for (int k = 0; k < NK; k++) {
            float bv = FLT_MAX; int bj = 0;
            for (int j = 0; j < NC; j++)
                if (!taken[j] && smax[j] < bv) { bv = smax[j]; bj = j; }  // strict < : lower idx wins ties
            taken[bj] = true; skeep[k] = bj;
        }
    }
    __syncthreads();
    if (tid < NK) {
        int kk = skeep[tid];
        int gi = d_sidx[b*NC + kk];
        d_kconf[b*NK + tid] = d_sconf[b*NC + kk];
        #pragma unroll
        for (int c = 0; c < 4; c++)
            d_kloc[(b*NK + tid)*4 + c] = loc[((size_t)b*P + gi)*4 + c];
    }
    __syncthreads();
    for (int t = tid; t < NK*DM; t += 128) {
        int k = t / DM, c = t % DM;
        int gi = d_sidx[b*NC + skeep[k]];
        d_kmask[(b*NK + k)*DM + c] = mask[((size_t)b*P + gi)*DM + c];
    }
    // AE: sum_k ae_loss_k * sum_{j>i_k} iou[i_k,j]*conf[i_k]*conf[j]
    float acc = 0.f;
    for (int t = tid; t < NK*NC; t += 128) {
        int k = t / NC, j = t % NC;
        int ik = skeep[k];
        if (j > ik) {
            const float* kl = &d_kloc[(b*NK + k)*4];
            float ael = 0.25f * (kl[0]*kl[0] + kl[1]*kl[1] + kl[2]*kl[2] + kl[3]*kl[3]);
            acc += ael * d_sconf[b*NC + ik] * d_sconf[b*NC + j] * siou[ik*NC + j];
        }
    }
    sred[tid] = acc;
    __syncthreads();
    for (int s = 64; s > 0; s >>= 1) {
        if (tid < s) sred[tid] += sred[tid + s];
        __syncthreads();
    }
    if (tid == 0) atomicAdd(&d_ae_acc, (double)sred[0] / (double)(B*NC*NC));
}

// ---- final_conf on 138x138 ----
__global__ void fconfK(const float* __restrict__ proto) {
    __shared__ float skm[B*NK*DM];
    __shared__ float skl[B*NK*4];
    __shared__ float skc[B*NK];
    int tid = threadIdx.x;
    for (int t = tid; t < B*NK*DM; t += 256) skm[t] = d_kmask[t];
    for (int t = tid; t < B*NK*4;  t += 256) skl[t] = d_kloc[t];
    for (int t = tid; t < B*NK;    t += 256) skc[t] = d_kconf[t];
    __syncthreads();
    int p = blockIdx.x*256 + tid;
    if (p >= B*HP*HP) return;
    int b = p / (HP*HP);
    int r = p % (HP*HP);
    int h = r / HP, w = r % HP;
    const float* pr = proto + (size_t)p * DM;
    float pv[DM];
    #pragma unroll
    for (int c = 0; c < DM; c += 4) {
        float4 v = *(const float4*)(pr + c);
        pv[c] = v.x; pv[c+1] = v.y; pv[c+2] = v.z; pv[c+3] = v.w;
    }
    float xs = (w + 0.5f) / (float)HP;
    float ys = (h + 0.5f) / (float)HP;
    float s1 = 0.f, s2 = 0.f;
    for (int k = 0; k < NK; k++) {
        const float* m = &skm[(b*NK + k)*DM];
        float d = 0.f;
        #pragma unroll
        for (int c = 0; c < DM; c++) d += pv[c] * m[c];
        float sig = 1.0f / (1.0f + expf(-d));
        const float* l = &skl[(b*NK + k)*4];
        float dx = (xs - l[0]) / (l[2] + 1e-4f);
        float dy = (ys - l[1]) / (l[3] + 1e-4f);
        float g = expf(-0.5f * (dx*dx + dy*dy));
        float mc = sig * g * skc[b*NK + k];
        s1 += mc;
        s2 += mc * mc;
    }
    float fc = 1.0f - s2 / (s1 + 1e-6f);
    if (fc != fc) fc = 0.f;                 // isnan -> 0
    d_fconf[p] = fc;
}

// ---- fused bilinear resize (half-pixel, clamp) + weighted variance ----
__global__ void varK(const float* __restrict__ original) {
    __shared__ float sred[256];
    int t = blockIdx.x*256 + threadIdx.x;
    float acc = 0.f;
    if (t < HIMG*HIMG) {
        int y = t / HIMG, x = t % HIMG;
        const float sf = (float)HP / (float)HIMG;
        float fx = (x + 0.5f)*sf - 0.5f;
        float fy = (y + 0.5f)*sf - 0.5f;
        float fx0 = floorf(fx), fy0 = floorf(fy);
        float tx = fx - fx0, ty = fy - fy0;
        int x0 = (int)fx0, y0 = (int)fy0;
        int x0c = min(max(x0, 0), HP-1), x1c = min(max(x0+1, 0), HP-1);
        int y0c = min(max(y0, 0), HP-1), y1c = min(max(y0+1, 0), HP-1);
        float w00 = (1.f-tx)*(1.f-ty), w01 = tx*(1.f-ty);
        float w10 = (1.f-tx)*ty,       w11 = tx*ty;
        float r0, r1;
        {
            const float* f = d_fconf;
            r0 = w00*f[y0c*HP+x0c] + w01*f[y0c*HP+x1c] + w10*f[y1c*HP+x0c] + w11*f[y1c*HP+x1c];
            f = d_fconf + HP*HP;
            r1 = w00*f[y0c*HP+x0c] + w01*f[y0c*HP+x1c] + w10*f[y1c*HP+x0c] + w11*f[y1c*HP+x1c];
        }
        float total = r0 + r1;
        float inv_t  = 1.0f / total;            // reference has no eps here
        float inv_te = 1.0f / (total + 1e-6f);
        #pragma unroll
        for (int c = 0; c < 3; c++) {
            float o0 = original[(0*3 + c)*HIMG*HIMG + t];
            float o1 = original[(1*3 + c)*HIMG*HIMG + t];
            float wm = (o0*r0 + o1*r1) * inv_t;
            float d0 = o0 - wm, d1 = o1 - wm;
            acc += (d0*d0*r0 + d1*d1*r1) * inv_te;
        }
    }
    sred[threadIdx.x] = acc;
    __syncthreads();
    for (int s = 128; s > 0; s >>= 1) {
        if (threadIdx.x < s) sred[threadIdx.x] += sred[threadIdx.x + s];
        __syncthreads();
    }
    if (threadIdx.x == 0) atomicAdd(&d_var_acc, (double)sred[0]);
}

__global__ void finK(float* out) {
    out[0] = (float)(d_var_acc / (double)HP * (double)B);
    out[1] = (float)d_ae_acc;
}

extern "C" void kernel_launch(void* const* d_in, const int* in_sizes, int n_in,
                              void* d_out, int out_size) {
    const float* original = (const float*)d_in[0];
    const float* loc      = (const float*)d_in[1];
    const float* conf     = (const float*)d_in[2];
    const float* mask     = (const float*)d_in[3];
    const float* proto    = (const float*)d_in[4];
    float* out = (float*)d_out;

    cudaFuncSetAttribute(topkK, cudaFuncAttributeMaxDynamicSharedMemorySize, P*(int)sizeof(float));

    initK<<<1, 1>>>();
    confpK<<<(B*P + 255)/256, 256>>>(conf);
    topkK<<<B, 1024, P*sizeof(float)>>>();
    gaussK<<<B*NC, 1024>>>(loc);
    iouK<<<B*NC, 256>>>();
    keepK<<<B, 128>>>(loc, mask);
    fconfK<<<(B*HP*HP + 255)/256, 256>>>(proto);
    varK<<<(HIMG*HIMG + 255)/256, 256>>>(original);
    finK<<<1, 1>>>(out);
}

// round 2
// speedup vs baseline: 2.1049x; 2.1049x over previous
#include <cuda_runtime.h>
#include <math.h>
#include <float.h>

#define B    2
#define P    19248
#define NC   100
#define NK   20
#define GP   1024   /* 32*32 */
#define HP   138
#define HIMG 550
#define DM   32
#define NBIN 1024
#define CAND 1024

__device__ float d_confp[B*P];
__device__ float d_sconf[B*NC];
__device__ int   d_sidx[B*NC];
__device__ float d_g[B*NC*GP];
__device__ float d_gsum[B*NC];
__device__ float d_iou[B*NC*NC];
__device__ float d_kloc[B*NK*4];
__device__ float d_kmask[B*NK*DM];
__device__ float d_kconf[B*NK];
__device__ float d_fconf[B*HP*HP];
__device__ unsigned d_hist[B*NBIN];
__device__ unsigned d_done;
__device__ double d_ae_acc;
__device__ double d_var_acc;

__global__ void initK() {
    int t = blockIdx.x * blockDim.x + threadIdx.x;
    if (t < B*NBIN) d_hist[t] = 0u;
    if (t == 0) { d_ae_acc = 0.0; d_var_acc = 0.0; d_done = 0u; }
}

// ---- conf softmax[:,1] + per-batch value histogram ----
__global__ void confpK(const float* __restrict__ conf) {
    int t = blockIdx.x * blockDim.x + threadIdx.x;
    if (t < B*P) {
        float c0 = conf[2*t], c1 = conf[2*t+1];
        float v = 1.0f / (1.0f + expf(c0 - c1));
        d_confp[t] = v;
        int b = t / P;
        int bucket = min(NBIN-1, max(0, (int)(v * (float)NBIN)));
        atomicAdd(&d_hist[b*NBIN + bucket], 1u);
    }
}

// ---- top-100 per batch: histogram threshold + compact + bitonic sort ----
__global__ void selectK() {
    __shared__ unsigned suf[NBIN];
    __shared__ unsigned long long cand[CAND];
    __shared__ int sT, scnt;
    __shared__ float wv[32];
    __shared__ int   wi[32];
    int b = blockIdx.x;
    int tid = threadIdx.x;     // 1024

    suf[tid] = d_hist[b*NBIN + tid];
    __syncthreads();
    // suffix sums (Hillis-Steele)
    for (int off = 1; off < NBIN; off <<= 1) {
        unsigned add = (tid + off < NBIN) ? suf[tid + off] : 0u;
        __syncthreads();
        suf[tid] += add;
        __syncthreads();
    }
    // largest bin T with suffix count >= NC
    if (suf[tid] >= NC && (tid == NBIN-1 || suf[tid+1] < NC)) sT = tid;
    if (tid == 0) scnt = 0;
    __syncthreads();
    int T = sT;
    unsigned total = suf[T];

    if (total <= CAND) {
        // compact candidates (bucket >= T)
        for (int p = tid; p < P; p += 1024) {
            float v = d_confp[b*P + p];
            int bucket = min(NBIN-1, max(0, (int)(v * (float)NBIN)));
            if (bucket >= T) {
                int pos = atomicAdd(&scnt, 1);
                cand[pos] = ((unsigned long long)__float_as_uint(v) << 32)
                          | (unsigned long long)(0xFFFFFFFFu - (unsigned)p);
            }
        }
        __syncthreads();
        int cnt = scnt;
        int N2 = (cnt <= 256) ? 256 : ((cnt <= 512) ? 512 : CAND);
        for (int i = cnt + tid; i < N2; i += 1024) cand[i] = 0ull;   // pad: sorts to tail
        __syncthreads();
        // bitonic sort descending over N2 (key = valbits|~idx -> value desc, idx asc)
        for (int k = 2; k <= N2; k <<= 1) {
            for (int j = k >> 1; j > 0; j >>= 1) {
                if (tid < N2) {
                    int p = tid ^ j;
                    if (p > tid) {
                        bool dirDesc = ((tid & k) == 0);
                        unsigned long long a = cand[tid], c = cand[p];
                        bool sw = dirDesc ? (a < c) : (a > c);
                        if (sw) { cand[tid] = c; cand[p] = a; }
                    }
                }
                __syncthreads();
            }
        }
        if (tid < NC) {
            unsigned long long key = cand[tid];
            d_sconf[b*NC + tid] = __uint_as_float((unsigned)(key >> 32));
            d_sidx[b*NC + tid]  = (int)(0xFFFFFFFFu - (unsigned)(key & 0xFFFFFFFFull));
        }
    } else {
        // pathological fallback: iterative argmax on global scratch (reuse d_g)
        float* sv = d_g + b*P;
        for (int p = tid; p < P; p += 1024) sv[p] = d_confp[b*P + p];
        __syncthreads();
        for (int it = 0; it < NC; it++) {
            float bv = -FLT_MAX; int bi = P;
            for (int p = tid; p < P; p += 1024) {
                float v = sv[p];
                if (v > bv) { bv = v; bi = p; }
            }
            #pragma unroll
            for (int off = 16; off > 0; off >>= 1) {
                float ov = __shfl_down_sync(0xffffffffu, bv, off);
                int   oi = __shfl_down_sync(0xffffffffu, bi, off);
                if (ov > bv || (ov == bv && oi < bi)) { bv = ov; bi = oi; }
            }
            if ((tid & 31) == 0) { wv[tid >> 5] = bv; wi[tid >> 5] = bi; }
            __syncthreads();
            if (tid < 32) {
                bv = wv[tid]; bi = wi[tid];
                #pragma unroll
                for (int off = 16; off > 0; off >>= 1) {
                    float ov = __shfl_down_sync(0xffffffffu, bv, off);
                    int   oi = __shfl_down_sync(0xffffffffu, bi, off);
                    if (ov > bv || (ov == bv && oi < bi)) { bv = ov; bi = oi; }
                }
                if (tid == 0) {
                    d_sconf[b*NC + it] = bv;
                    d_sidx[b*NC + it]  = bi;
                    sv[bi] = -FLT_MAX;
                }
            }
            __syncthreads();
        }
    }
}

// ---- render 32x32 gaussians + per-box sums ----
__global__ void gaussK(const float* __restrict__ loc) {
    __shared__ float red[32];
    int blk = blockIdx.x;                // b*NC + i
    int b = blk / NC;
    int tid = threadIdx.x;               // 1024
    int gidx = d_sidx[blk];
    const float* l = loc + ((size_t)b*P + gidx) * 4;
    float cx = l[0], cy = l[1], w = l[2], h = l[3];
    int y = tid >> 5, x = tid & 31;
    float xs = (x + 0.5f) / 32.0f;
    float ys = (y + 0.5f) / 32.0f;
    float dx = (xs - cx) / (w + 1e-4f);
    float dy = (ys - cy) / (h + 1e-4f);
    float g = expf(-0.5f * (dx*dx + dy*dy));
    d_g[blk*GP + tid] = g;
    float s = g;
    #pragma unroll
    for (int off = 16; off > 0; off >>= 1) s += __shfl_down_sync(0xffffffffu, s, off);
    if ((tid & 31) == 0) red[tid >> 5] = s;
    __syncthreads();
    if (tid < 32) {
        s = red[tid];
        #pragma unroll
        for (int off = 16; off > 0; off >>= 1) s += __shfl_down_sync(0xffffffffu, s, off);
        if (tid == 0) d_gsum[blk] = s;
    }
}

// ---- pairwise gaussian IoU, only j > i ----
__global__ void iouK() {
    __shared__ float sgi[GP];
    int blk = blockIdx.x;                // b*NC + i
    int b = blk / NC, i = blk % NC;
    int tid = threadIdx.x;               // 256
    const float* gi = d_g + blk*GP;
    for (int e = tid; e < GP; e += 256) sgi[e] = gi[e];
    __syncthreads();
    int warp = tid >> 5, lane = tid & 31;
    float si = d_gsum[blk];
    for (int j = i + 1 + warp; j < NC; j += 8) {
        const float* gj = d_g + (b*NC + j)*GP;
        float acc = 0.f;
        #pragma unroll 4
        for (int e = lane; e < GP; e += 32) acc += fminf(sgi[e], gj[e]);
        #pragma unroll
        for (int off = 16; off > 0; off >>= 1) acc += __shfl_down_sync(0xffffffffu, acc, off);
        if (lane == 0) {
            float sj = d_gsum[b*NC + j];
            d_iou[(b*NC + i)*NC + j] = acc / (si + sj - acc);
        }
    }
}

// ---- iou_max, keep-20 (bitonic), gathers, AE loss term ----
__global__ void keepK(const float* __restrict__ loc, const float* __restrict__ mask) {
    __shared__ float siou[NC*NC];        // 40 KB
    __shared__ unsigned long long kk[128];
    __shared__ int   skeep[NK];
    __shared__ float sred[128];
    int b = blockIdx.x, tid = threadIdx.x;   // 128 threads
    for (int t = tid; t < NC*NC; t += 128) {
        int i = t / NC, j = t % NC;
        siou[t] = (j > i) ? d_iou[(b*NC + i)*NC + j] : 0.f;
    }
    __syncthreads();
    // iou_max per column + pack (ioumax asc, idx asc) keys
    {
        unsigned long long key = 0xFFFFFFFFFFFFFFFFull;   // pad -> sorts to tail (asc)
        if (tid < NC) {
            float m = 0.f;
            for (int i = 0; i < tid; i++) m = fmaxf(m, siou[i*NC + tid]);
            key = ((unsigned long long)__float_as_uint(m) << 32) | (unsigned)tid;
        }
        kk[tid] = key;
    }
    __syncthreads();
    // bitonic sort ascending over 128
    for (int k = 2; k <= 128; k <<= 1) {
        for (int j = k >> 1; j > 0; j >>= 1) {
            int p = tid ^ j;
            if (p > tid) {
                bool dirAsc = ((tid & k) == 0);
                unsigned long long a = kk[tid], c = kk[p];
                bool sw = dirAsc ? (a > c) : (a < c);
                if (sw) { kk[tid] = c; kk[p] = a; }
            }
            __syncthreads();
        }
    }
    if (tid < NK) {
        int kidx = (int)(kk[tid] & 0xFFFFFFFFull);
        skeep[tid] = kidx;
        int gi = d_sidx[b*NC + kidx];
        d_kconf[b*NK + tid] = d_sconf[b*NC + kidx];
        #pragma unroll
        for (int c = 0; c < 4; c++)
            d_kloc[(b*NK + tid)*4 + c] = loc[((size_t)b*P + gi)*4 + c];
    }
    __syncthreads();
    for (int t = tid; t < NK*DM; t += 128) {
        int k = t / DM, c = t % DM;
        int gi = d_sidx[b*NC + skeep[k]];
        d_kmask[(b*NK + k)*DM + c] = mask[((size_t)b*P + gi)*DM + c];
    }
    // AE: sum_k ae_loss_k * sum_{j>i_k} iou[i_k,j]*conf[i_k]*conf[j]
    float acc = 0.f;
    for (int t = tid; t < NK*NC; t += 128) {
        int k = t / NC, j = t % NC;
        int ik = skeep[k];
        if (j > ik) {
            const float* kl = &d_kloc[(b*NK + k)*4];
            float ael = 0.25f * (kl[0]*kl[0] + kl[1]*kl[1] + kl[2]*kl[2] + kl[3]*kl[3]);
            acc += ael * d_sconf[b*NC + ik] * d_sconf[b*NC + j] * siou[ik*NC + j];
        }
    }
    sred[tid] = acc;
    __syncthreads();
    for (int s = 64; s > 0; s >>= 1) {
        if (tid < s) sred[tid] += sred[tid + s];
        __syncthreads();
    }
    if (tid == 0) atomicAdd(&d_ae_acc, (double)sred[0] / (double)(B*NC*NC));
}

// ---- final_conf on 138x138 ----
__global__ void fconfK(const float* __restrict__ proto) {
    __shared__ float skm[B*NK*DM];
    __shared__ float skl[B*NK*4];
    __shared__ float skc[B*NK];
    int tid = threadIdx.x;
    for (int t = tid; t < B*NK*DM; t += 256) skm[t] = d_kmask[t];
    for (int t = tid; t < B*NK*4;  t += 256) skl[t] = d_kloc[t];
    for (int t = tid; t < B*NK;    t += 256) skc[t] = d_kconf[t];
    __syncthreads();
    int p = blockIdx.x*256 + tid;
    if (p >= B*HP*HP) return;
    int b = p / (HP*HP);
    int r = p % (HP*HP);
    int h = r / HP, w = r % HP;
    const float* pr = proto + (size_t)p * DM;
    float pv[DM];
    #pragma unroll
    for (int c = 0; c < DM; c += 4) {
        float4 v = *(const float4*)(pr + c);
        pv[c] = v.x; pv[c+1] = v.y; pv[c+2] = v.z; pv[c+3] = v.w;
    }
    float xs = (w + 0.5f) / (float)HP;
    float ys = (h + 0.5f) / (float)HP;
    float s1 = 0.f, s2 = 0.f;
    for (int k = 0; k < NK; k++) {
        const float* m = &skm[(b*NK + k)*DM];
        float d = 0.f;
        #pragma unroll
        for (int c = 0; c < DM; c++) d += pv[c] * m[c];
        float sig = 1.0f / (1.0f + expf(-d));
        const float* l = &skl[(b*NK + k)*4];
        float dx = (xs - l[0]) / (l[2] + 1e-4f);
        float dy = (ys - l[1]) / (l[3] + 1e-4f);
        float g = expf(-0.5f * (dx*dx + dy*dy));
        float mc = sig * g * skc[b*NK + k];
        s1 += mc;
        s2 += mc * mc;
    }
    float fc = 1.0f - s2 / (s1 + 1e-6f);
    if (fc != fc) fc = 0.f;                 // isnan -> 0
    d_fconf[p] = fc;
}

// ---- fused bilinear resize + weighted variance + finisher ----
__global__ void varK(const float* __restrict__ original, float* __restrict__ out) {
    __shared__ float sred[256];
    int t = blockIdx.x*256 + threadIdx.x;
    float acc = 0.f;
    if (t < HIMG*HIMG) {
        int y = t / HIMG, x = t % HIMG;
        const float sf = (float)HP / (float)HIMG;
        float fx = (x + 0.5f)*sf - 0.5f;
        float fy = (y + 0.5f)*sf - 0.5f;
        float fx0 = floorf(fx), fy0 = floorf(fy);
        float tx = fx - fx0, ty = fy - fy0;
        int x0 = (int)fx0, y0 = (int)fy0;
        int x0c = min(max(x0, 0), HP-1), x1c = min(max(x0+1, 0), HP-1);
        int y0c = min(max(y0, 0), HP-1), y1c = min(max(y0+1, 0), HP-1);
        float w00 = (1.f-tx)*(1.f-ty), w01 = tx*(1.f-ty);
        float w10 = (1.f-tx)*ty,       w11 = tx*ty;
        float r0, r1;
        {
            const float* f = d_fconf;
            r0 = w00*f[y0c*HP+x0c] + w01*f[y0c*HP+x1c] + w10*f[y1c*HP+x0c] + w11*f[y1c*HP+x1c];
            f = d_fconf + HP*HP;
            r1 = w00*f[y0c*HP+x0c] + w01*f[y0c*HP+x1c] + w10*f[y1c*HP+x0c] + w11*f[y1c*HP+x1c];
        }
        float total = r0 + r1;
        float inv_t  = 1.0f / total;            // reference has no eps here
        float inv_te = 1.0f / (total + 1e-6f);
        #pragma unroll
        for (int c = 0; c < 3; c++) {
            float o0 = original[(0*3 + c)*HIMG*HIMG + t];
            float o1 = original[(1*3 + c)*HIMG*HIMG + t];
            float wm = (o0*r0 + o1*r1) * inv_t;
            float d0 = o0 - wm, d1 = o1 - wm;
            acc += (d0*d0*r0 + d1*d1*r1) * inv_te;
        }
    }
    sred[threadIdx.x] = acc;
    __syncthreads();
    for (int s = 128; s > 0; s >>= 1) {
        if (threadIdx.x < s) sred[threadIdx.x] += sred[threadIdx.x + s];
        __syncthreads();
    }
    if (threadIdx.x == 0) {
        atomicAdd(&d_var_acc, (double)sred[0]);
        __threadfence();
        unsigned ticket = atomicAdd(&d_done, 1u);
        if (ticket == gridDim.x - 1) {
            __threadfence();
            out[0] = (float)(d_var_acc / (double)HP * (double)B);
            out[1] = (float)d_ae_acc;
        }
    }
}

extern "C" void kernel_launch(void* const* d_in, const int* in_sizes, int n_in,
                              void* d_out, int out_size) {
    const float* original = (const float*)d_in[0];
    const float* loc      = (const float*)d_in[1];
    const float* conf     = (const float*)d_in[2];
    const float* mask     = (const float*)d_in[3];
    const float* proto    = (const float*)d_in[4];
    float* out = (float*)d_out;

    initK<<<(B*NBIN + 1023)/1024, 1024>>>();
    confpK<<<(B*P + 255)/256, 256>>>(conf);
    selectK<<<B, 1024>>>();
    gaussK<<<B*NC, 1024>>>(loc);
    iouK<<<B*NC, 256>>>();
    keepK<<<B, 128>>>(loc, mask);
    fconfK<<<(B*HP*HP + 255)/256, 256>>>(proto);
    varK<<<(HIMG*HIMG + 255)/256, 256>>>(original, out);
}

// round 4
// speedup vs baseline: 2.4122x; 1.1460x over previous
#include <cuda_runtime.h>
#include <math.h>
#include <float.h>

#define B    2
#define P    19248
#define NC   100
#define NK   20
#define GP   1024   /* 32*32 */
#define HP   138
#define HIMG 550
#define DM   32
#define NBIN 1024
#define CAND 1024
#define NBLK 148
#define NTH  1024

__device__ float d_confp[B*P];
__device__ float d_sconf[B*NC];
__device__ int   d_sidx[B*NC];
__device__ float d_g[B*NC*GP];
__device__ float d_gsum[B*NC];
__device__ float d_iou[B*NC*NC];
__device__ float d_kloc[B*NK*4];
__device__ float d_kmask[B*NK*DM];
__device__ float d_kconf[B*NK];
__device__ float d_fconf[B*HP*HP];
__device__ float d_ae[B];
__device__ double d_var_acc;
__device__ unsigned bar_count;            // zero-init at module load
__device__ volatile unsigned bar_gen;

// software grid barrier: safe because grid(148) <= #SMs and 1 block/SM occupancy
__device__ __forceinline__ void gridsync() {
    __threadfence();
    __syncthreads();
    if (threadIdx.x == 0) {
        unsigned gen = bar_gen;
        unsigned arrived = atomicAdd(&bar_count, 1u);
        if (arrived == (unsigned)gridDim.x - 1u) {
            bar_count = 0u;
            __threadfence();
            bar_gen = gen + 1u;
        } else {
            while (bar_gen == gen) { }
        }
    }
    __syncthreads();
    __threadfence();
}

__global__ void __launch_bounds__(NTH, 1)
fusedK(const float* __restrict__ original, const float* __restrict__ loc,
       const float* __restrict__ conf, const float* __restrict__ mask,
       const float* __restrict__ proto, float* __restrict__ out)
{
    __shared__ unsigned s_hist[NBIN];
    __shared__ unsigned long long s_cand[CAND];       // 8 KB (also used by keep bitonic)
    __shared__ float s_iou[NC*NC];                    // 40 KB
    __shared__ float s_gi[GP];                        // 4 KB
    __shared__ float s_red[NTH/32];
    __shared__ float s_red2[256];
    __shared__ int   s_T, s_cnt;
    __shared__ int   s_keep[NK];
    __shared__ float s_km[B*NK*DM];
    __shared__ float s_kl[B*NK*4];
    __shared__ float s_kc[B*NK];

    const int tid  = threadIdx.x;
    const int warp = tid >> 5, lane = tid & 31;

    // ================= Phase 0: select top-100 per batch (blocks 0..B-1) ======
    if (blockIdx.x == 0 && tid == 0) d_var_acc = 0.0;
    if (blockIdx.x < B) {
        int b = blockIdx.x;
        s_hist[tid] = 0u;
        __syncthreads();
        for (int p = tid; p < P; p += NTH) {
            float c0 = conf[(size_t)(b*P + p)*2], c1 = conf[(size_t)(b*P + p)*2 + 1];
            float v = 1.0f / (1.0f + expf(c0 - c1));
            d_confp[b*P + p] = v;
            int bucket = min(NBIN-1, max(0, (int)(v * (float)NBIN)));
            atomicAdd(&s_hist[bucket], 1u);
        }
        __syncthreads();
        // suffix sums over bins
        for (int off = 1; off < NBIN; off <<= 1) {
            unsigned add = (tid + off < NBIN) ? s_hist[tid + off] : 0u;
            __syncthreads();
            s_hist[tid] += add;
            __syncthreads();
        }
        if (s_hist[tid] >= NC && (tid == NBIN-1 || s_hist[tid+1] < NC)) s_T = tid;
        if (tid == 0) s_cnt = 0;
        __syncthreads();
        int T = s_T;
        unsigned total = s_hist[T];

        if (total <= CAND) {
            for (int p = tid; p < P; p += NTH) {
                float v = d_confp[b*P + p];
                int bucket = min(NBIN-1, max(0, (int)(v * (float)NBIN)));
                if (bucket >= T) {
                    int pos = atomicAdd(&s_cnt, 1);
                    s_cand[pos] = ((unsigned long long)__float_as_uint(v) << 32)
                                | (unsigned long long)(0xFFFFFFFFu - (unsigned)p);
                }
            }
            __syncthreads();
            int cnt = s_cnt;
            int N2 = (cnt <= 256) ? 256 : ((cnt <= 512) ? 512 : CAND);
            for (int i = cnt + tid; i < N2; i += NTH) s_cand[i] = 0ull;
            __syncthreads();
            for (int k = 2; k <= N2; k <<= 1) {
                for (int j = k >> 1; j > 0; j >>= 1) {
                    if (tid < N2) {
                        int p = tid ^ j;
                        if (p > tid) {
                            bool dirDesc = ((tid & k) == 0);
                            unsigned long long a = s_cand[tid], c = s_cand[p];
                            bool sw = dirDesc ? (a < c) : (a > c);
                            if (sw) { s_cand[tid] = c; s_cand[p] = a; }
                        }
                    }
                    __syncthreads();
                }
            }
            if (tid < NC) {
                unsigned long long key = s_cand[tid];
                d_sconf[b*NC + tid] = __uint_as_float((unsigned)(key >> 32));
                d_sidx[b*NC + tid]  = (int)(0xFFFFFFFFu - (unsigned)(key & 0xFFFFFFFFull));
            }
        } else {
            // pathological fallback: iterative argmax on global scratch (d_g unused yet)
            float* sv = d_g + b*P;
            for (int p = tid; p < P; p += NTH) sv[p] = d_confp[b*P + p];
            __syncthreads();
            for (int it = 0; it < NC; it++) {
                float bv = -FLT_MAX; int bi = P;
                for (int p = tid; p < P; p += NTH) {
                    float v = sv[p];
                    if (v > bv) { bv = v; bi = p; }
                }
                #pragma unroll
                for (int off = 16; off > 0; off >>= 1) {
                    float ov = __shfl_down_sync(0xffffffffu, bv, off);
                    int   oi = __shfl_down_sync(0xffffffffu, bi, off);
                    if (ov > bv || (ov == bv && oi < bi)) { bv = ov; bi = oi; }
                }
                if (lane == 0) { s_red[warp] = bv; ((int*)s_hist)[warp] = bi; }
                __syncthreads();
                if (tid < 32) {
                    bv = s_red[tid]; bi = ((int*)s_hist)[tid];
                    #pragma unroll
                    for (int off = 16; off > 0; off >>= 1) {
                        float ov = __shfl_down_sync(0xffffffffu, bv, off);
                        int   oi = __shfl_down_sync(0xffffffffu, bi, off);
                        if (ov > bv || (ov == bv && oi < bi)) { bv = ov; bi = oi; }
                    }
                    if (tid == 0) {
                        d_sconf[b*NC + it] = bv;
                        d_sidx[b*NC + it]  = bi;
                        sv[bi] = -FLT_MAX;
                    }
                }
                __syncthreads();
            }
        }
    }
    gridsync();

    // ================= Phase 1: gaussians + sums =============================
    for (int vb = blockIdx.x; vb < B*NC; vb += NBLK) {
        int bb = vb / NC;
        int gidx = d_sidx[vb];
        const float* l = loc + ((size_t)bb*P + gidx) * 4;
        float cx = l[0], cy = l[1], w = l[2], h = l[3];
        int y = tid >> 5, x = tid & 31;
        float xs = (x + 0.5f) / 32.0f;
        float ys = (y + 0.5f) / 32.0f;
        float dx = (xs - cx) / (w + 1e-4f);
        float dy = (ys - cy) / (h + 1e-4f);
        float g = expf(-0.5f * (dx*dx + dy*dy));
        d_g[vb*GP + tid] = g;
        float s = g;
        #pragma unroll
        for (int off = 16; off > 0; off >>= 1) s += __shfl_down_sync(0xffffffffu, s, off);
        if (lane == 0) s_red[warp] = s;
        __syncthreads();
        if (tid < 32) {
            s = s_red[tid];
            #pragma unroll
            for (int off = 16; off > 0; off >>= 1) s += __shfl_down_sync(0xffffffffu, s, off);
            if (tid == 0) d_gsum[vb] = s;
        }
        __syncthreads();
    }
    gridsync();

    // ================= Phase 2: pairwise IoU (j > i) =========================
    for (int vb = blockIdx.x; vb < B*NC; vb += NBLK) {
        int bb = vb / NC, i = vb % NC;
        __syncthreads();
        s_gi[tid] = d_g[vb*GP + tid];
        __syncthreads();
        float si = d_gsum[vb];
        for (int j = i + 1 + warp; j < NC; j += 32) {
            const float* gj = d_g + (bb*NC + j)*GP;
            float acc = 0.f;
            #pragma unroll 4
            for (int e = lane; e < GP; e += 32) acc += fminf(s_gi[e], gj[e]);
            #pragma unroll
            for (int off = 16; off > 0; off >>= 1) acc += __shfl_down_sync(0xffffffffu, acc, off);
            if (lane == 0) {
                float sj = d_gsum[bb*NC + j];
                d_iou[(bb*NC + i)*NC + j] = acc / (si + sj - acc);
            }
        }
    }
    gridsync();

    // ================= Phase 3: keep-20, gathers, AE =========================
    if (blockIdx.x < B) {
        int b = blockIdx.x;
        for (int t = tid; t < NC*NC; t += NTH) {
            int i = t / NC, j = t % NC;
            s_iou[t] = (j > i) ? d_iou[(b*NC + i)*NC + j] : 0.f;
        }
        __syncthreads();
        {
            unsigned long long key = 0xFFFFFFFFFFFFFFFFull;
            if (tid < NC) {
                float m = 0.f;
                for (int i = 0; i < tid; i++) m = fmaxf(m, s_iou[i*NC + tid]);
                key = ((unsigned long long)__float_as_uint(m) << 32) | (unsigned)tid;
            }
            if (tid < 128) s_cand[tid] = key;
        }
        __syncthreads();
        // bitonic ascending over 128 keys (iou_max asc, idx asc)
        for (int k = 2; k <= 128; k <<= 1) {
            for (int j = k >> 1; j > 0; j >>= 1) {
                if (tid < 128) {
                    int p = tid ^ j;
                    if (p > tid) {
                        bool dirAsc = ((tid & k) == 0);
                        unsigned long long a = s_cand[tid], c = s_cand[p];
                        bool sw = dirAsc ? (a > c) : (a < c);
                        if (sw) { s_cand[tid] = c; s_cand[p] = a; }
                    }
                }
                __syncthreads();
            }
        }
        if (tid < NK) {
            int kidx = (int)(s_cand[tid] & 0xFFFFFFFFull);
            s_keep[tid] = kidx;
            int gi = d_sidx[b*NC + kidx];
            d_kconf[b*NK + tid] = d_sconf[b*NC + kidx];
            #pragma unroll
            for (int c = 0; c < 4; c++)
                d_kloc[(b*NK + tid)*4 + c] = loc[((size_t)b*P + gi)*4 + c];
        }
        __syncthreads();
        for (int t = tid; t < NK*DM; t += NTH) {
            int k = t / DM, c = t % DM;
            int gi = d_sidx[b*NC + s_keep[k]];
            d_kmask[(b*NK + k)*DM + c] = mask[((size_t)b*P + gi)*DM + c];
        }
        float acc = 0.f;
        for (int t = tid; t < NK*NC; t += NTH) {
            int k = t / NC, j = t % NC;
            int ik = s_keep[k];
            if (j > ik) {
                float l0 = d_kloc[(b*NK + k)*4 + 0], l1 = d_kloc[(b*NK + k)*4 + 1];
                float l2 = d_kloc[(b*NK + k)*4 + 2], l3 = d_kloc[(b*NK + k)*4 + 3];
                float ael = 0.25f * (l0*l0 + l1*l1 + l2*l2 + l3*l3);
                acc += ael * d_sconf[b*NC + ik] * d_sconf[b*NC + j] * s_iou[ik*NC + j];
            }
        }
        #pragma unroll
        for (int off = 16; off > 0; off >>= 1) acc += __shfl_down_sync(0xffffffffu, acc, off);
        if (lane == 0) s_red[warp] = acc;
        __syncthreads();
        if (tid < 32) {
            acc = s_red[tid];
            #pragma unroll
            for (int off = 16; off > 0; off >>= 1) acc += __shfl_down_sync(0xffffffffu, acc, off);
            if (tid == 0) d_ae[b] = acc / (float)(B*NC*NC);
        }
    }
    gridsync();

    // ================= Phase 4: final_conf on 138x138 ========================
    for (int t = tid; t < B*NK*DM; t += NTH) s_km[t] = d_kmask[t];
    for (int t = tid; t < B*NK*4;  t += NTH) s_kl[t] = d_kloc[t];
    for (int t = tid; t < B*NK;    t += NTH) s_kc[t] = d_kconf[t];
    __syncthreads();
    {
        int p = blockIdx.x*NTH + tid;
        if (p < B*HP*HP) {
            int b = p / (HP*HP);
            int r = p % (HP*HP);
            int h = r / HP, w = r % HP;
            const float* pr = proto + (size_t)p * DM;
            float pv[DM];
            #pragma unroll
            for (int c = 0; c < DM; c += 4) {
                float4 v = *(const float4*)(pr + c);
                pv[c] = v.x; pv[c+1] = v.y; pv[c+2] = v.z; pv[c+3] = v.w;
            }
            float xs = (w + 0.5f) / (float)HP;
            float ys = (h + 0.5f) / (float)HP;
            float s1 = 0.f, s2 = 0.f;
            for (int k = 0; k < NK; k++) {
                const float* m = &s_km[(b*NK + k)*DM];
                float d = 0.f;
                #pragma unroll
                for (int c = 0; c < DM; c++) d += pv[c] * m[c];
                float sig = 1.0f / (1.0f + expf(-d));
                float dx = (xs - s_kl[(b*NK+k)*4+0]) / (s_kl[(b*NK+k)*4+2] + 1e-4f);
                float dy = (ys - s_kl[(b*NK+k)*4+1]) / (s_kl[(b*NK+k)*4+3] + 1e-4f);
                float g = expf(-0.5f * (dx*dx + dy*dy));
                float mc = sig * g * s_kc[b*NK + k];
                s1 += mc;
                s2 += mc * mc;
            }
            float fc = 1.0f - s2 / (s1 + 1e-6f);
            if (fc != fc) fc = 0.f;
            d_fconf[p] = fc;
        }
    }
    gridsync();

    // ================= Phase 5: resize + weighted variance ===================
    {
        float acc = 0.f;
        for (int t = blockIdx.x*NTH + tid; t < HIMG*HIMG; t += NBLK*NTH) {
            int y = t / HIMG, x = t % HIMG;
            const float sf = (float)HP / (float)HIMG;
            float fx = (x + 0.5f)*sf - 0.5f;
            float fy = (y + 0.5f)*sf - 0.5f;
            float fx0 = floorf(fx), fy0 = floorf(fy);
            float tx = fx - fx0, ty = fy - fy0;
            int x0 = (int)fx0, y0 = (int)fy0;
            int x0c = min(max(x0, 0), HP-1), x1c = min(max(x0+1, 0), HP-1);
            int y0c = min(max(y0, 0), HP-1), y1c = min(max(y0+1, 0), HP-1);
            float w00 = (1.f-tx)*(1.f-ty), w01 = tx*(1.f-ty);
            float w10 = (1.f-tx)*ty,       w11 = tx*ty;
            const float* f = d_fconf;
            float r0 = w00*f[y0c*HP+x0c] + w01*f[y0c*HP+x1c] + w10*f[y1c*HP+x0c] + w11*f[y1c*HP+x1c];
            f = d_fconf + HP*HP;
            float r1 = w00*f[y0c*HP+x0c] + w01*f[y0c*HP+x1c] + w10*f[y1c*HP+x0c] + w11*f[y1c*HP+x1c];
            float total = r0 + r1;
            float inv_t  = 1.0f / total;            // reference has no eps here
            float inv_te = 1.0f / (total + 1e-6f);
            #pragma unroll
            for (int c = 0; c < 3; c++) {
                float o0 = original[(0*3 + c)*HIMG*HIMG + t];
                float o1 = original[(1*3 + c)*HIMG*HIMG + t];
                float wm = (o0*r0 + o1*r1) * inv_t;
                float d0 = o0 - wm, d1 = o1 - wm;
                acc += (d0*d0*r0 + d1*d1*r1) * inv_te;
            }
        }
        s_red2[tid & 255] = 0.f;   // init not needed; use full-width reduction instead
        #pragma unroll
        for (int off = 16; off > 0; off >>= 1) acc += __shfl_down_sync(0xffffffffu, acc, off);
        if (lane == 0) s_red[warp] = acc;
        __syncthreads();
        if (tid < 32) {
            acc = s_red[tid];
            #pragma unroll
            for (int off = 16; off > 0; off >>= 1) acc += __shfl_down_sync(0xffffffffu, acc, off);
            if (tid == 0) atomicAdd(&d_var_acc, (double)acc);
        }
    }
    gridsync();

    // ================= Phase 6: finish =======================================
    if (blockIdx.x == 0 && tid == 0) {
        out[0] = (float)(d_var_acc / (double)HP * (double)B);
        out[1] = d_ae[0] + d_ae[1];
    }
}

extern "C" void kernel_launch(void* const* d_in, const int* in_sizes, int n_in,
                              void* d_out, int out_size) {
    const float* original = (const float*)d_in[0];
    const float* loc      = (const float*)d_in[1];
    const float* conf     = (const float*)d_in[2];
    const float* mask     = (const float*)d_in[3];
    const float* proto    = (const float*)d_in[4];
    float* out = (float*)d_out;

    fusedK<<<NBLK, NTH>>>(original, loc, conf, mask, proto, out);
}

// round 5
// speedup vs baseline: 2.8015x; 1.1614x over previous
#include <cuda_runtime.h>
#include <math.h>
#include <float.h>

#define B    2
#define P    19248
#define NC   100
#define NK   20
#define HP   138
#define HIMG 550
#define DM   32
#define NBIN 1024
#define CAND 1024
#define NBLK 148
#define NTH  1024
#define SF   (138.0f/550.0f)
#define MAXFR 5

__device__ float d_confp[B*P];
__device__ float d_sconf[B*NC];
__device__ int   d_sidx[B*NC];
__device__ float d_iou[B*NC*NC];
__device__ unsigned d_ioumax[B*NC];      // float-as-uint max (values >= 0)
__device__ float d_kloc[B*NK*4];
__device__ float d_kmask[B*NK*DM];
__device__ float d_kconf[B*NK];
__device__ float d_ae[B];
__device__ double d_var_acc;
__device__ unsigned d_hist[B*NBIN];
__device__ unsigned d_done;
__device__ unsigned bar_count;
__device__ volatile unsigned bar_gen;

// grid-wide barrier: grid(148) <= #SMs, 1 block/SM => all co-resident
__device__ __forceinline__ void gridsync() {
    __threadfence();
    __syncthreads();
    if (threadIdx.x == 0) {
        unsigned gen = bar_gen;
        unsigned arrived = atomicAdd(&bar_count, 1u);
        if (arrived == (unsigned)gridDim.x - 1u) {
            bar_count = 0u;
            __threadfence();
            bar_gen = gen + 1u;
        } else {
            while (bar_gen == gen) { }
        }
    }
    __syncthreads();
    __threadfence();
}

__device__ __forceinline__ void l2prefetch(const void* p) {
    asm volatile("prefetch.global.L2 [%0];" :: "l"(p));
}

__global__ void __launch_bounds__(NTH, 1)
fusedK(const float* __restrict__ original, const float* __restrict__ loc,
       const float* __restrict__ conf, const float* __restrict__ mask,
       const float* __restrict__ proto, float* __restrict__ out)
{
    __shared__ union {
        struct { unsigned hist[NBIN]; unsigned long long cand[CAND]; } p0;
        struct { float ax[NC*32]; float ay[NC*32]; float gsum[NC]; float loc4[NC*4]; } p1;
        struct { float iou[NC*NC]; unsigned long long kk[128]; } p2;
        struct { float fc[2*MAXFR*HP]; float km[B*NK*DM]; float kl[B*NK*4]; float kc[B*NK]; } p3;
    } u;
    __shared__ float s_red[32];
    __shared__ int   s_redi[32];
    __shared__ int   s_T, s_cnt;
    __shared__ int   s_keep[NK];

    const int tid  = threadIdx.x;
    const int warp = tid >> 5, lane = tid & 31;
    const int bid  = blockIdx.x;

    // ===== Phase 0a: conf_p + histogram (blocks 0..31); others L2-prefetch =====
    if (bid < 32) {
        int b = bid >> 4, s = bid & 15;
        u.p0.hist[tid] = 0u;
        __syncthreads();
        int p0 = s * (P/16), p1 = (s+1) * (P/16);
        for (int p = p0 + tid; p < p1; p += NTH) {
            float2 c2 = *(const float2*)(conf + (size_t)(b*P + p)*2);
            float v = 1.0f / (1.0f + expf(c2.x - c2.y));
            d_confp[b*P + p] = v;
            int bucket = min(NBIN-1, max(0, (int)(v * (float)NBIN)));
            atomicAdd(&u.p0.hist[bucket], 1u);
        }
        __syncthreads();
        unsigned c = u.p0.hist[tid];
        if (c) atomicAdd(&d_hist[b*NBIN + tid], c);
    } else {
        // prefetch original (7.26MB) + proto (4.87MB) into L2
        const size_t sz1 = (size_t)B*3*HIMG*HIMG*4;
        const size_t sz2 = (size_t)B*HP*HP*DM*4;
        size_t lines1 = sz1 >> 7, lines2 = sz2 >> 7;
        size_t start = (size_t)(bid - 32) * NTH + tid;
        size_t stride = (size_t)(NBLK - 32) * NTH;
        const char* o = (const char*)original;
        const char* q = (const char*)proto;
        for (size_t l = start; l < lines1; l += stride) l2prefetch(o + (l << 7));
        for (size_t l = start; l < lines2; l += stride) l2prefetch(q + (l << 7));
    }
    gridsync();

    // ===== Phase 0b: threshold + compact + sort top-100 (blocks 0..B-1) =====
    if (bid < B) {
        int b = bid;
        u.p0.hist[tid] = d_hist[b*NBIN + tid];
        __syncthreads();
        d_hist[b*NBIN + tid] = 0u;                     // reset for next launch
        for (int off = 1; off < NBIN; off <<= 1) {
            unsigned add = (tid + off < NBIN) ? u.p0.hist[tid + off] : 0u;
            __syncthreads();
            u.p0.hist[tid] += add;
            __syncthreads();
        }
        if (u.p0.hist[tid] >= NC && (tid == NBIN-1 || u.p0.hist[tid+1] < NC)) s_T = tid;
        if (tid == 0) s_cnt = 0;
        __syncthreads();
        int T = s_T;
        unsigned total = u.p0.hist[T];

        if (total <= CAND) {
            for (int p = tid; p < P; p += NTH) {
                float v = d_confp[b*P + p];
                int bucket = min(NBIN-1, max(0, (int)(v * (float)NBIN)));
                if (bucket >= T) {
                    int pos = atomicAdd(&s_cnt, 1);
                    u.p0.cand[pos] = ((unsigned long long)__float_as_uint(v) << 32)
                                   | (unsigned long long)(0xFFFFFFFFu - (unsigned)p);
                }
            }
            __syncthreads();
            int cnt = s_cnt;
            int N2 = (cnt <= 256) ? 256 : ((cnt <= 512) ? 512 : CAND);
            for (int i = cnt + tid; i < N2; i += NTH) u.p0.cand[i] = 0ull;
            __syncthreads();
            for (int k = 2; k <= N2; k <<= 1) {
                for (int j = k >> 1; j > 0; j >>= 1) {
                    if (tid < N2) {
                        int p = tid ^ j;
                        if (p > tid) {
                            bool dirDesc = ((tid & k) == 0);
                            unsigned long long a = u.p0.cand[tid], c = u.p0.cand[p];
                            bool sw = dirDesc ? (a < c) : (a > c);
                            if (sw) { u.p0.cand[tid] = c; u.p0.cand[p] = a; }
                        }
                    }
                    __syncthreads();
                }
            }
            if (tid < NC) {
                unsigned long long key = u.p0.cand[tid];
                d_sconf[b*NC + tid] = __uint_as_float((unsigned)(key >> 32));
                d_sidx[b*NC + tid]  = (int)(0xFFFFFFFFu - (unsigned)(key & 0xFFFFFFFFull));
            }
        } else {
            // fallback: iterative argmax, destructive on d_confp
            float* sv = d_confp + b*P;
            for (int it = 0; it < NC; it++) {
                float bv = -FLT_MAX; int bi = P;
                for (int p = tid; p < P; p += NTH) {
                    float v = sv[p];
                    if (v > bv) { bv = v; bi = p; }
                }
                #pragma unroll
                for (int off = 16; off > 0; off >>= 1) {
                    float ov = __shfl_down_sync(0xffffffffu, bv, off);
                    int   oi = __shfl_down_sync(0xffffffffu, bi, off);
                    if (ov > bv || (ov == bv && oi < bi)) { bv = ov; bi = oi; }
                }
                if (lane == 0) { s_red[warp] = bv; s_redi[warp] = bi; }
                __syncthreads();
                if (tid < 32) {
                    bv = s_red[tid]; bi = s_redi[tid];
                    #pragma unroll
                    for (int off = 16; off > 0; off >>= 1) {
                        float ov = __shfl_down_sync(0xffffffffu, bv, off);
                        int   oi = __shfl_down_sync(0xffffffffu, bi, off);
                        if (ov > bv || (ov == bv && oi < bi)) { bv = ov; bi = oi; }
                    }
                    if (tid == 0) {
                        d_sconf[b*NC + it] = bv;
                        d_sidx[b*NC + it]  = bi;
                        sv[bi] = -FLT_MAX;
                    }
                }
                __syncthreads();
            }
        }
    }
    gridsync();

    // ===== Phase 1: separable-gaussian pairwise IoU (j > i) =====
    {
        int curBatch = -1;
        for (int task = bid; task < B*NC; task += NBLK) {
            int bb = task / NC, i = task % NC;
            if (bb != curBatch) {
                __syncthreads();
                // stage kept-100 loc
                if (tid < NC*4) {
                    int box = tid >> 2, c = tid & 3;
                    int gi = d_sidx[bb*NC + box];
                    u.p1.loc4[tid] = loc[((size_t)bb*P + gi)*4 + c];
                }
                __syncthreads();
                // build ax/ay tables: 100 boxes x 32
                for (int t = tid; t < NC*32; t += NTH) {
                    int box = t >> 5, e = t & 31;
                    float cx = u.p1.loc4[box*4+0], cy = u.p1.loc4[box*4+1];
                    float w  = u.p1.loc4[box*4+2], h  = u.p1.loc4[box*4+3];
                    float s  = (e + 0.5f) / 32.0f;
                    float dx = (s - cx) / (w + 1e-4f);
                    float dy = (s - cy) / (h + 1e-4f);
                    u.p1.ax[t] = expf(-0.5f * dx * dx);
                    u.p1.ay[t] = expf(-0.5f * dy * dy);
                }
                __syncthreads();
                if (tid < NC) {
                    float sx = 0.f, sy = 0.f;
                    #pragma unroll
                    for (int e = 0; e < 32; e++) { sx += u.p1.ax[tid*32+e]; sy += u.p1.ay[tid*32+e]; }
                    u.p1.gsum[tid] = sx * sy;
                }
                __syncthreads();
                curBatch = bb;
            }
            float gix = u.p1.ax[i*32 + lane];
            float giy[32];
            #pragma unroll
            for (int y = 0; y < 32; y++) giy[y] = u.p1.ay[i*32 + y] * gix;
            float si = u.p1.gsum[i];
            for (int j = i + 1 + warp; j < NC; j += 32) {
                float axj = u.p1.ax[j*32 + lane];
                float acc = 0.f;
                #pragma unroll
                for (int y = 0; y < 32; y++)
                    acc += fminf(giy[y], u.p1.ay[j*32 + y] * axj);
                #pragma unroll
                for (int off = 16; off > 0; off >>= 1)
                    acc += __shfl_down_sync(0xffffffffu, acc, off);
                if (lane == 0) {
                    float sj = u.p1.gsum[j];
                    float iouv = acc / (si + sj - acc);
                    d_iou[(bb*NC + i)*NC + j] = iouv;
                    atomicMax(&d_ioumax[bb*NC + j], __float_as_uint(iouv));
                }
            }
        }
    }
    gridsync();

    // ===== Phase 2: keep-20, gathers, AE (blocks 0..B-1) =====
    if (bid < B) {
        int b = bid;
        for (int t = tid; t < NC*NC; t += NTH) {
            int i = t / NC, j = t % NC;
            u.p2.iou[t] = (j > i) ? d_iou[(b*NC + i)*NC + j] : 0.f;
        }
        {
            unsigned long long key = 0xFFFFFFFFFFFFFFFFull;
            if (tid < NC) {
                float m = __uint_as_float(d_ioumax[b*NC + tid]);
                d_ioumax[b*NC + tid] = 0u;           // reset for next launch
                key = ((unsigned long long)__float_as_uint(m) << 32) | (unsigned)tid;
            }
            if (tid < 128) u.p2.kk[tid] = key;
        }
        __syncthreads();
        for (int k = 2; k <= 128; k <<= 1) {
            for (int j = k >> 1; j > 0; j >>= 1) {
                if (tid < 128) {
                    int p = tid ^ j;
                    if (p > tid) {
                        bool dirAsc = ((tid & k) == 0);
                        unsigned long long a = u.p2.kk[tid], c = u.p2.kk[p];
                        bool sw = dirAsc ? (a > c) : (a < c);
                        if (sw) { u.p2.kk[tid] = c; u.p2.kk[p] = a; }
                    }
                }
                __syncthreads();
            }
        }
        if (tid < NK) {
            int kidx = (int)(u.p2.kk[tid] & 0xFFFFFFFFull);
            s_keep[tid] = kidx;
            int gi = d_sidx[b*NC + kidx];
            d_kconf[b*NK + tid] = d_sconf[b*NC + kidx];
            #pragma unroll
            for (int c = 0; c < 4; c++)
                d_kloc[(b*NK + tid)*4 + c] = loc[((size_t)b*P + gi)*4 + c];
        }
        __syncthreads();
        for (int t = tid; t < NK*DM; t += NTH) {
            int k = t / DM, c = t % DM;
            int gi = d_sidx[b*NC + s_keep[k]];
            d_kmask[(b*NK + k)*DM + c] = mask[((size_t)b*P + gi)*DM + c];
        }
        float acc = 0.f;
        for (int t = tid; t < NK*NC; t += NTH) {
            int k = t / NC, j = t % NC;
            int ik = s_keep[k];
            if (j > ik) {
                float l0 = d_kloc[(b*NK + k)*4 + 0], l1 = d_kloc[(b*NK + k)*4 + 1];
                float l2 = d_kloc[(b*NK + k)*4 + 2], l3 = d_kloc[(b*NK + k)*4 + 3];
                float ael = 0.25f * (l0*l0 + l1*l1 + l2*l2 + l3*l3);
                acc += ael * d_sconf[b*NC + ik] * d_sconf[b*NC + j] * u.p2.iou[ik*NC + j];
            }
        }
        #pragma unroll
        for (int off = 16; off > 0; off >>= 1) acc += __shfl_down_sync(0xffffffffu, acc, off);
        if (lane == 0) s_red[warp] = acc;
        __syncthreads();
        if (tid < 32) {
            acc = s_red[tid];
            #pragma unroll
            for (int off = 16; off > 0; off >>= 1) acc += __shfl_down_sync(0xffffffffu, acc, off);
            if (tid == 0) d_ae[b] = acc / (float)(B*NC*NC);
        }
    }
    gridsync();

    // ===== Phase 3: per-strip fconf recompute + bilinear resize + variance =====
    {
        for (int t = tid; t < B*NK*DM; t += NTH) u.p3.km[t] = d_kmask[t];
        for (int t = tid; t < B*NK*4;  t += NTH) u.p3.kl[t] = d_kloc[t];
        for (int t = tid; t < B*NK;    t += NTH) u.p3.kc[t] = d_kconf[t];
        int y0 = bid * HIMG / NBLK, y1 = (bid + 1) * HIMG / NBLK;
        float fyMin = (y0 + 0.5f)*SF - 0.5f;
        float fyMax = (y1 - 0.5f)*SF - 0.5f;
        int fr0 = max((int)floorf(fyMin), 0);
        int fr1 = min((int)floorf(fyMax) + 1, HP-1);
        int nfr = fr1 - fr0 + 1;                      // <= MAXFR
        __syncthreads();
        // fconf for the needed rows, both batches
        for (int t = tid; t < B*nfr*HP; t += NTH) {
            int b = t / (nfr*HP);
            int r = (t / HP) % nfr;
            int w = t % HP;
            int fh = fr0 + r;
            const float* pr = proto + (size_t)(b*HP*HP + fh*HP + w) * DM;
            float pv[DM];
            #pragma unroll
            for (int c = 0; c < DM; c += 4) {
                float4 v = *(const float4*)(pr + c);
                pv[c] = v.x; pv[c+1] = v.y; pv[c+2] = v.z; pv[c+3] = v.w;
            }
            float xs = (w + 0.5f) / (float)HP;
            float ys = (fh + 0.5f) / (float)HP;
            float s1 = 0.f, s2 = 0.f;
            for (int k = 0; k < NK; k++) {
                const float* m = &u.p3.km[(b*NK + k)*DM];
                float d = 0.f;
                #pragma unroll
                for (int c = 0; c < DM; c++) d += pv[c] * m[c];
                float sig = 1.0f / (1.0f + expf(-d));
                float dx = (xs - u.p3.kl[(b*NK+k)*4+0]) / (u.p3.kl[(b*NK+k)*4+2] + 1e-4f);
                float dy = (ys - u.p3.kl[(b*NK+k)*4+1]) / (u.p3.kl[(b*NK+k)*4+3] + 1e-4f);
                float g = expf(-0.5f * (dx*dx + dy*dy));
                float mc = sig * g * u.p3.kc[b*NK + k];
                s1 += mc;
                s2 += mc * mc;
            }
            float fc = 1.0f - s2 / (s1 + 1e-6f);
            if (fc != fc) fc = 0.f;
            u.p3.fc[(b*MAXFR + r)*HP + w] = fc;
        }
        __syncthreads();
        // variance over this block's rows
        float acc = 0.f;
        int npix = (y1 - y0) * HIMG;
        for (int idx = tid; idx < npix; idx += NTH) {
            int y = y0 + idx / HIMG, x = idx % HIMG;
            int t = y*HIMG + x;
            float fx = (x + 0.5f)*SF - 0.5f;
            float fy = (y + 0.5f)*SF - 0.5f;
            float fx0 = floorf(fx), fy0 = floorf(fy);
            float tx = fx - fx0, ty = fy - fy0;
            int x0 = (int)fx0, yy0 = (int)fy0;
            int x0c = min(max(x0, 0), HP-1), x1c = min(max(x0+1, 0), HP-1);
            int y0c = min(max(yy0, 0), HP-1), y1c = min(max(yy0+1, 0), HP-1);
            int r0i = y0c - fr0, r1i = y1c - fr0;
            float w00 = (1.f-tx)*(1.f-ty), w01 = tx*(1.f-ty);
            float w10 = (1.f-tx)*ty,       w11 = tx*ty;
            const float* f0 = &u.p3.fc[0];
            const float* f1 = &u.p3.fc[MAXFR*HP];
            float r0 = w00*f0[r0i*HP+x0c] + w01*f0[r0i*HP+x1c] + w10*f0[r1i*HP+x0c] + w11*f0[r1i*HP+x1c];
            float r1 = w00*f1[r0i*HP+x0c] + w01*f1[r0i*HP+x1c] + w10*f1[r1i*HP+x0c] + w11*f1[r1i*HP+x1c];
            float total = r0 + r1;
            float inv_t  = 1.0f / total;              // reference has no eps here
            float inv_te = 1.0f / (total + 1e-6f);
            #pragma unroll
            for (int c = 0; c < 3; c++) {
                float o0 = original[(0*3 + c)*HIMG*HIMG + t];
                float o1 = original[(1*3 + c)*HIMG*HIMG + t];
                float wm = (o0*r0 + o1*r1) * inv_t;
                float d0 = o0 - wm, d1 = o1 - wm;
                acc += (d0*d0*r0 + d1*d1*r1) * inv_te;
            }
        }
        #pragma unroll
        for (int off = 16; off > 0; off >>= 1) acc += __shfl_down_sync(0xffffffffu, acc, off);
        if (lane == 0) s_red[warp] = acc;
        __syncthreads();
        if (tid < 32) {
            acc = s_red[tid];
            #pragma unroll
            for (int off = 16; off > 0; off >>= 1) acc += __shfl_down_sync(0xffffffffu, acc, off);
            if (tid == 0) {
                atomicAdd(&d_var_acc, (double)acc);
                __threadfence();
                unsigned ticket = atomicAdd(&d_done, 1u);
                if (ticket == (unsigned)gridDim.x - 1u) {
                    __threadfence();
                    out[0] = (float)(d_var_acc / (double)HP * (double)B);
                    out[1] = d_ae[0] + d_ae[1];
                    d_var_acc = 0.0;                  // reset for next launch
                    d_done = 0u;
                }
            }
        }
    }
}

extern "C" void kernel_launch(void* const* d_in, const int* in_sizes, int n_in,
                              void* d_out, int out_size) {
    const float* original = (const float*)d_in[0];
    const float* loc      = (const float*)d_in[1];
    const float* conf     = (const float*)d_in[2];
    const float* mask     = (const float*)d_in[3];
    const float* proto    = (const float*)d_in[4];
    float* out = (float*)d_out;

    fusedK<<<NBLK, NTH>>>(original, loc, conf, mask, proto, out);
}

// round 6
// speedup vs baseline: 3.2851x; 1.1726x over previous
#include <cuda_runtime.h>
#include <math.h>
#include <float.h>

#define B    2
#define P    19248
#define NC   100
#define NK   20
#define HP   138
#define HIMG 550
#define DM   32
#define NBIN 1024
#define CAND 1024
#define NBLK 148
#define NTH  1024
#define SF   (138.0f/550.0f)
#define MAXFR 5
#define NPAIR (NC*(NC-1)/2)       /* 4950 */
#define A1   (2*NC-1)             /* 199 */

__device__ float d_sconf[B*NC];
__device__ int   d_sidx[B*NC];
__device__ float d_iou[B*NC*NC];
__device__ float d_ae[B];
__device__ double d_var_acc;
__device__ unsigned d_done;
__device__ unsigned bar_count;
__device__ volatile unsigned bar_gen;

// grid-wide barrier: grid(148) <= #SMs, 1 block/SM => all co-resident
__device__ __forceinline__ void gridsync() {
    __threadfence();
    __syncthreads();
    if (threadIdx.x == 0) {
        unsigned gen = bar_gen;
        unsigned arrived = atomicAdd(&bar_count, 1u);
        if (arrived == (unsigned)gridDim.x - 1u) {
            bar_count = 0u;
            __threadfence();
            bar_gen = gen + 1u;
        } else {
            while (bar_gen == gen) { }
        }
    }
    __syncthreads();
    __threadfence();
}

__device__ __forceinline__ void l2prefetch(const void* p) {
    asm volatile("prefetch.global.L2 [%0];" :: "l"(p));
}

// triangular pair decode: t in [0, NPAIR) -> (i, j), j > i
__device__ __forceinline__ void pairDecode(int t, int& i, int& j) {
    int ii = (int)(((float)A1 - sqrtf((float)(A1*A1) - 8.0f*(float)t)) * 0.5f);
    if (ii < 0) ii = 0;
    if (ii > NC-2) ii = NC-2;
    while (ii > 0 && ii*(A1-ii)/2 > t) --ii;
    while (ii < NC-2 && (ii+1)*(A1-(ii+1))/2 <= t) ++ii;
    i = ii;
    j = ii + 1 + (t - ii*(A1-ii)/2);
}

__global__ void __launch_bounds__(NTH, 1)
fusedK(const float* __restrict__ original, const float* __restrict__ loc,
       const float* __restrict__ conf, const float* __restrict__ mask,
       const float* __restrict__ proto, float* __restrict__ out)
{
    __shared__ union {
        struct { unsigned hist[NBIN]; unsigned long long cand[CAND]; } a;
        struct { float ax[NC*32]; float ay[NC*32]; float gsum[NC]; float loc4[NC*4]; } b;
        struct { float m[2*NC]; } c;
        struct { float fc[2*MAXFR*HP]; } d;
    } u;
    __shared__ float s_km[B*NK*DM];
    __shared__ float s_kl[B*NK*4];
    __shared__ float s_kc[B*NK];
    __shared__ int   s_keep[B*NK];
    __shared__ float s_red[32];
    __shared__ int   s_T, s_cnt;

    const int tid  = threadIdx.x;
    const int warp = tid >> 5, lane = tid & 31;
    const int bid  = blockIdx.x;

    // ===== Phase A: full top-100 selection per batch (blocks 0,1); rest prefetch =====
    if (bid < B) {
        int b = bid;
        u.a.hist[tid] = 0u;
        if (tid == 0) s_cnt = 0;
        __syncthreads();
        // pass 1: sigmoid + histogram
        for (int p = tid; p < P; p += NTH) {
            float2 c2 = *(const float2*)(conf + (size_t)(b*P + p)*2);
            float v = 1.0f / (1.0f + expf(c2.x - c2.y));
            int bucket = min(NBIN-1, max(0, (int)(v * (float)NBIN)));
            atomicAdd(&u.a.hist[bucket], 1u);
        }
        __syncthreads();
        // suffix sums
        for (int off = 1; off < NBIN; off <<= 1) {
            unsigned add = (tid + off < NBIN) ? u.a.hist[tid + off] : 0u;
            __syncthreads();
            u.a.hist[tid] += add;
            __syncthreads();
        }
        if (u.a.hist[tid] >= NC && (tid == NBIN-1 || u.a.hist[tid+1] < NC)) s_T = tid;
        __syncthreads();
        int T = s_T;
        unsigned total = u.a.hist[T];
        __syncthreads();

        if (total <= CAND) {
            // pass 2: compact candidates
            for (int p = tid; p < P; p += NTH) {
                float2 c2 = *(const float2*)(conf + (size_t)(b*P + p)*2);
                float v = 1.0f / (1.0f + expf(c2.x - c2.y));
                int bucket = min(NBIN-1, max(0, (int)(v * (float)NBIN)));
                if (bucket >= T) {
                    int pos = atomicAdd(&s_cnt, 1);
                    u.a.cand[pos] = ((unsigned long long)__float_as_uint(v) << 32)
                                  | (unsigned long long)(0xFFFFFFFFu - (unsigned)p);
                }
            }
            __syncthreads();
            int cnt = s_cnt;
            // rank-by-counting: rank = #keys greater than mine (desc order, idx tiebreak)
            if (tid < cnt) {
                unsigned long long mykey = u.a.cand[tid];
                int rank = 0;
                for (int c2 = 0; c2 < cnt; c2++)
                    rank += (u.a.cand[c2] > mykey) ? 1 : 0;
                if (rank < NC) {
                    d_sconf[b*NC + rank] = __uint_as_float((unsigned)(mykey >> 32));
                    d_sidx[b*NC + rank]  = (int)(0xFFFFFFFFu - (unsigned)(mykey & 0xFFFFFFFFull));
                }
            }
        } else {
            // pathological fallback: non-destructive iterative max (recompute sigmoid)
            unsigned long long prev = 0xFFFFFFFFFFFFFFFFull;
            for (int it = 0; it < NC; it++) {
                unsigned long long best = 0ull;
                for (int p = tid; p < P; p += NTH) {
                    float2 c2 = *(const float2*)(conf + (size_t)(b*P + p)*2);
                    float v = 1.0f / (1.0f + expf(c2.x - c2.y));
                    unsigned long long key = ((unsigned long long)__float_as_uint(v) << 32)
                                           | (unsigned long long)(0xFFFFFFFFu - (unsigned)p);
                    if (key < prev && key > best) best = key;
                }
                #pragma unroll
                for (int off = 16; off > 0; off >>= 1) {
                    unsigned long long o = __shfl_down_sync(0xffffffffu, best, off);
                    if (o > best) best = o;
                }
                if (lane == 0) ((unsigned long long*)u.a.cand)[warp] = best;
                __syncthreads();
                if (tid < 32) {
                    best = ((unsigned long long*)u.a.cand)[tid];
                    #pragma unroll
                    for (int off = 16; off > 0; off >>= 1) {
                        unsigned long long o = __shfl_down_sync(0xffffffffu, best, off);
                        if (o > best) best = o;
                    }
                    if (tid == 0) {
                        d_sconf[b*NC + it] = __uint_as_float((unsigned)(best >> 32));
                        d_sidx[b*NC + it]  = (int)(0xFFFFFFFFu - (unsigned)(best & 0xFFFFFFFFull));
                        ((unsigned long long*)u.a.cand)[0] = best;
                    }
                }
                __syncthreads();
                prev = ((unsigned long long*)u.a.cand)[0];
                __syncthreads();
            }
        }
    } else {
        // prefetch original (7.26MB) + proto (4.87MB) into L2
        const size_t lines1 = ((size_t)B*3*HIMG*HIMG*4) >> 7;
        const size_t lines2 = ((size_t)B*HP*HP*DM*4) >> 7;
        size_t start = (size_t)(bid - B) * NTH + tid;
        size_t stride = (size_t)(NBLK - B) * NTH;
        const char* o = (const char*)original;
        const char* q = (const char*)proto;
        for (size_t l = start; l < lines1; l += stride) l2prefetch(o + (l << 7));
        for (size_t l = start; l < lines2; l += stride) l2prefetch(q + (l << 7));
    }
    gridsync();

    // ===== Phase B: pairwise IoU, flat warp distribution, per-batch smem tables =====
    {
        const int gwarp = bid * 32 + warp;       // 0..4735
        for (int bb = 0; bb < B; bb++) {
            // stage kept-100 loc
            if (tid < NC*4) {
                int box = tid >> 2, c = tid & 3;
                int gi = d_sidx[bb*NC + box];
                u.b.loc4[tid] = loc[((size_t)bb*P + gi)*4 + c];
            }
            __syncthreads();
            // separable gaussian tables
            for (int t = tid; t < NC*32; t += NTH) {
                int box = t >> 5, e = t & 31;
                float s = (e + 0.5f) / 32.0f;
                float dx = (s - u.b.loc4[box*4+0]) / (u.b.loc4[box*4+2] + 1e-4f);
                float dy = (s - u.b.loc4[box*4+1]) / (u.b.loc4[box*4+3] + 1e-4f);
                u.b.ax[t] = expf(-0.5f * dx * dx);
                u.b.ay[t] = expf(-0.5f * dy * dy);
            }
            __syncthreads();
            if (tid < NC) {
                float sx = 0.f, sy = 0.f;
                #pragma unroll
                for (int e = 0; e < 32; e++) { sx += u.b.ax[tid*32+e]; sy += u.b.ay[tid*32+e]; }
                u.b.gsum[tid] = sx * sy;
            }
            __syncthreads();
            for (int t = gwarp; t < NPAIR; t += NBLK*32) {
                int i, j;
                pairDecode(t, i, j);
                float gix = u.b.ax[i*32 + lane];
                float axj = u.b.ax[j*32 + lane];
                float acc = 0.f;
                #pragma unroll
                for (int y = 0; y < 32; y++)
                    acc += fminf(u.b.ay[i*32 + y] * gix, u.b.ay[j*32 + y] * axj);
                #pragma unroll
                for (int off = 16; off > 0; off >>= 1)
                    acc += __shfl_down_sync(0xffffffffu, acc, off);
                if (lane == 0) {
                    float denom = u.b.gsum[i] + u.b.gsum[j] - acc;
                    d_iou[(bb*NC + i)*NC + j] = acc / denom;
                }
            }
            __syncthreads();
        }
    }
    gridsync();

    // ===== Phase C: keep-20 + gathers (ALL blocks, redundant); AE on blocks 0,1 =====
    {
        // col-max of triu iou, both batches
        if (tid < 2*NC) {
            int bb = tid / NC, j = tid % NC;
            float m = 0.f;
            for (int i = 0; i < j; i++) m = fmaxf(m, d_iou[(bb*NC + i)*NC + j]);
            u.c.m[tid] = m;
        }
        __syncthreads();
        // rank-by-counting ascending (m, j)
        if (tid < 2*NC) {
            int bb = tid / NC, j = tid % NC;
            float m = u.c.m[tid];
            int rank = 0;
            for (int j2 = 0; j2 < NC; j2++) {
                float m2 = u.c.m[bb*NC + j2];
                rank += (m2 < m || (m2 == m && j2 < j)) ? 1 : 0;
            }
            if (rank < NK) s_keep[bb*NK + rank] = j;
        }
        __syncthreads();
        // gather kept conf/loc
        if (tid < B*NK) {
            int bb = tid / NK;
            int j = s_keep[tid];
            int gi = d_sidx[bb*NC + j];
            s_kc[tid] = d_sconf[bb*NC + j];
            #pragma unroll
            for (int c = 0; c < 4; c++)
                s_kl[tid*4 + c] = loc[((size_t)bb*P + gi)*4 + c];
        }
        __syncthreads();
        // gather kept mask
        for (int t = tid; t < B*NK*DM; t += NTH) {
            int bb = t / (NK*DM);
            int k = (t / DM) % NK, c = t % DM;
            int gi = d_sidx[bb*NC + s_keep[bb*NK + k]];
            s_km[t] = mask[((size_t)bb*P + gi)*DM + c];
        }
        __syncthreads();
        // AE term (blocks 0,1 only)
        if (bid < B) {
            int b = bid;
            float acc = 0.f;
            for (int t = tid; t < NK*NC; t += NTH) {
                int k = t / NC, j = t % NC;
                int ik = s_keep[b*NK + k];
                if (j > ik) {
                    float l0 = s_kl[(b*NK + k)*4 + 0], l1 = s_kl[(b*NK + k)*4 + 1];
                    float l2 = s_kl[(b*NK + k)*4 + 2], l3 = s_kl[(b*NK + k)*4 + 3];
                    float ael = 0.25f * (l0*l0 + l1*l1 + l2*l2 + l3*l3);
                    acc += ael * d_sconf[b*NC + ik] * d_sconf[b*NC + j]
                               * d_iou[(b*NC + ik)*NC + j];
                }
            }
            #pragma unroll
            for (int off = 16; off > 0; off >>= 1) acc += __shfl_down_sync(0xffffffffu, acc, off);
            if (lane == 0) s_red[warp] = acc;
            __syncthreads();
            if (tid < 32) {
                acc = s_red[tid];
                #pragma unroll
                for (int off = 16; off > 0; off >>= 1) acc += __shfl_down_sync(0xffffffffu, acc, off);
                if (tid == 0) d_ae[b] = acc / (float)(B*NC*NC);
            }
        }
        __syncthreads();
    }

    // ===== Phase D: per-strip fconf + bilinear resize + variance + ticket finish =====
    {
        int y0 = bid * HIMG / NBLK, y1 = (bid + 1) * HIMG / NBLK;
        float fyMin = (y0 + 0.5f)*SF - 0.5f;
        float fyMax = (y1 - 0.5f)*SF - 0.5f;
        int fr0 = max((int)floorf(fyMin), 0);
        int fr1 = min((int)floorf(fyMax) + 1, HP-1);
        int nfr = fr1 - fr0 + 1;                      // <= MAXFR
        // fconf rows needed by this strip, both batches
        for (int t = tid; t < B*nfr*HP; t += NTH) {
            int b = t / (nfr*HP);
            int r = (t / HP) % nfr;
            int w = t % HP;
            int fh = fr0 + r;
            const float* pr = proto + (size_t)(b*HP*HP + fh*HP + w) * DM;
            float pv[DM];
            #pragma unroll
            for (int c = 0; c < DM; c += 4) {
                float4 v = *(const float4*)(pr + c);
                pv[c] = v.x; pv[c+1] = v.y; pv[c+2] = v.z; pv[c+3] = v.w;
            }
            float xs = (w + 0.5f) / (float)HP;
            float ys = (fh + 0.5f) / (float)HP;
            float s1 = 0.f, s2 = 0.f;
            for (int k = 0; k < NK; k++) {
                const float* m = &s_km[(b*NK + k)*DM];
                float d = 0.f;
                #pragma unroll
                for (int c = 0; c < DM; c++) d += pv[c] * m[c];
                float sig = 1.0f / (1.0f + __expf(-d));
                float dx = (xs - s_kl[(b*NK+k)*4+0]) / (s_kl[(b*NK+k)*4+2] + 1e-4f);
                float dy = (ys - s_kl[(b*NK+k)*4+1]) / (s_kl[(b*NK+k)*4+3] + 1e-4f);
                float g = __expf(-0.5f * (dx*dx + dy*dy));
                float mc = sig * g * s_kc[b*NK + k];
                s1 += mc;
                s2 += mc * mc;
            }
            float fc = 1.0f - s2 / (s1 + 1e-6f);
            if (fc != fc) fc = 0.f;
            u.d.fc[(b*MAXFR + r)*HP + w] = fc;
        }
        __syncthreads();
        // variance over this block's rows
        float acc = 0.f;
        int npix = (y1 - y0) * HIMG;
        for (int idx = tid; idx < npix; idx += NTH) {
            int y = y0 + idx / HIMG, x = idx % HIMG;
            int t = y*HIMG + x;
            float fx = (x + 0.5f)*SF - 0.5f;
            float fy = (y + 0.5f)*SF - 0.5f;
            float fx0 = floorf(fx), fy0 = floorf(fy);
            float tx = fx - fx0, ty = fy - fy0;
            int x0 = (int)fx0, yy0 = (int)fy0;
            int x0c = min(max(x0, 0), HP-1), x1c = min(max(x0+1, 0), HP-1);
            int y0c = min(max(yy0, 0), HP-1), y1c = min(max(yy0+1, 0), HP-1);
            int r0i = y0c - fr0, r1i = y1c - fr0;
            float w00 = (1.f-tx)*(1.f-ty), w01 = tx*(1.f-ty);
            float w10 = (1.f-tx)*ty,       w11 = tx*ty;
            const float* f0 = &u.d.fc[0];
            const float* f1 = &u.d.fc[MAXFR*HP];
            float r0 = w00*f0[r0i*HP+x0c] + w01*f0[r0i*HP+x1c] + w10*f0[r1i*HP+x0c] + w11*f0[r1i*HP+x1c];
            float r1 = w00*f1[r0i*HP+x0c] + w01*f1[r0i*HP+x1c] + w10*f1[r1i*HP+x0c] + w11*f1[r1i*HP+x1c];
            float total = r0 + r1;
            float inv_t  = 1.0f / total;              // reference has no eps here
            float inv_te = 1.0f / (total + 1e-6f);
            #pragma unroll
            for (int c = 0; c < 3; c++) {
                float o0 = original[(0*3 + c)*HIMG*HIMG + t];
                float o1 = original[(1*3 + c)*HIMG*HIMG + t];
                float wm = (o0*r0 + o1*r1) * inv_t;
                float d0 = o0 - wm, d1 = o1 - wm;
                acc += (d0*d0*r0 + d1*d1*r1) * inv_te;
            }
        }
        #pragma unroll
        for (int off = 16; off > 0; off >>= 1) acc += __shfl_down_sync(0xffffffffu, acc, off);
        if (lane == 0) s_red[warp] = acc;
        __syncthreads();
        if (tid < 32) {
            acc = s_red[tid];
            #pragma unroll
            for (int off = 16; off > 0; off >>= 1) acc += __shfl_down_sync(0xffffffffu, acc, off);
            if (tid == 0) {
                atomicAdd(&d_var_acc, (double)acc);
                __threadfence();
                unsigned ticket = atomicAdd(&d_done, 1u);
                if (ticket == (unsigned)gridDim.x - 1u) {
                    __threadfence();
                    out[0] = (float)(d_var_acc / (double)HP * (double)B);
                    out[1] = d_ae[0] + d_ae[1];
                    d_var_acc = 0.0;                  // reset for next replay
                    d_done = 0u;
                }
            }
        }
    }
}

extern "C" void kernel_launch(void* const* d_in, const int* in_sizes, int n_in,
                              void* d_out, int out_size) {
    const float* original = (const float*)d_in[0];
    const float* loc      = (const float*)d_in[1];
    const float* conf     = (const float*)d_in[2];
    const float* mask     = (const float*)d_in[3];
    const float* proto    = (const float*)d_in[4];
    float* out = (float*)d_out;

    fusedK<<<NBLK, NTH>>>(original, loc, conf, mask, proto, out);
}